// round 8
// baseline (speedup 1.0000x reference)
#include <cuda_runtime.h>
#include <cuda_bf16.h>

// DiceLoss fused, software-pipelined: softmax over C=19 + per-class dice.
// logits [8,19,512,512] f32; targets [8,512,512] int32.
// 2 pixels/thread, 4 loop iterations with register double-buffer prefetch:
// next iteration's 19 float2 loads are in flight during the current
// iteration's reduction phase (kills the convoy memory-idle gaps seen in R7).

#define CC      19
#define LOG_HW  18
#define HW      (1 << LOG_HW)          // 262,144
#define BATCH   8
#define NPIX    (BATCH * HW)           // 2,097,152
#define THREADS 256
#define NBLOCKS 1024
#define ITERS   4                      // 1024*256*4 pairs * 2 px = NPIX
#define PAIR_STRIDE (NBLOCKS * THREADS)        // 262,144 pairs
#define BASE_STEP   ((size_t)2 * CC * HW)      // pixel stride 2*HW => b += 2
#define IGN     255

__device__ float    g_ps[CC];
__device__ float    g_in[CC];
__device__ float    g_ct[CC];
__device__ unsigned g_tick;

__global__ void __launch_bounds__(THREADS, 3) dice_pipe(
    const float* __restrict__ logits, const int* __restrict__ targets,
    float* __restrict__ out)
{
    __shared__ float s_ps[CC], s_in[CC], s_ct[CC];
    __shared__ int   s_last;
    const int tid  = threadIdx.x;
    const int lane = tid & 31;
    if (tid < CC) { s_ps[tid] = 0.f; s_in[tid] = 0.f; s_ct[tid] = 0.f; }
    __syncthreads();

    const int q0 = blockIdx.x * THREADS + tid;   // pair id in [0, 262144)
    const int p0 = q0 << 1;                      // pixel id (batch 0 or 1)
    const int b0 = p0 >> LOG_HW;
    const int hw = p0 & (HW - 1);
    const float* base = logits + (((size_t)b0 * CC) << LOG_HW) + hw;
    const int*   tptr = targets + p0;

    // ---------------- prologue: load iteration 0 ----------------
    float2 x[CC];
    int2   tt;
    #pragma unroll
    for (int c = 0; c < CC; c++)
        x[c] = *(const float2*)(base + ((size_t)c << LOG_HW));
    tt = *(const int2*)tptr;

    #pragma unroll
    for (int it = 0; it < ITERS; it++) {
        // ---- consume x: exp, denom, gather; pack exps to bf16x2 ----
        int t0 = tt.x, t1 = tt.y;
        float v0 = (t0 == IGN) ? 0.f : 1.f;
        float v1 = (t1 == IGN) ? 0.f : 1.f;
        t0 = (t0 == IGN || (unsigned)t0 >= CC) ? 0 : t0;
        t1 = (t1 == IGN || (unsigned)t1 >= CC) ? 0 : t1;

        __nv_bfloat162 e01[CC];
        float d0 = 0.f, d1 = 0.f, ge0 = 0.f, ge1 = 0.f;
        #pragma unroll
        for (int c = 0; c < CC; c++) {
            float ex = __expf(x[c].x);
            float ey = __expf(x[c].y);
            d0 += ex; d1 += ey;
            if (c == t0) ge0 = ex;
            if (c == t1) ge1 = ey;
            e01[c] = __floats2bfloat162_rn(ex, ey);
        }

        // ---- prefetch next iteration (loads fly during reduction) ----
        if (it < ITERS - 1) {
            base += BASE_STEP;
            tptr += 2 * PAIR_STRIDE;
            #pragma unroll
            for (int c = 0; c < CC; c++)
                x[c] = *(const float2*)(base + ((size_t)c << LOG_HW));
            tt = *(const int2*)tptr;
        }

        // ---- reduction phase (overlapped with prefetched loads) ----
        const float r0 = v0 * __fdividef(1.f, d0);
        const float r1 = v1 * __fdividef(1.f, d1);

        atomicAdd(&s_in[t0], ge0 * r0);
        atomicAdd(&s_in[t1], ge1 * r1);
        atomicAdd(&s_ct[t0], v0);
        atomicAdd(&s_ct[t1], v1);

        #pragma unroll
        for (int c = 0; c < CC; c++) {
            float2 pr = __bfloat1622float2(e01[c]);
            float a = pr.x * r0 + pr.y * r1;
            // depth-3 butterfly: 8-lane partial sums (4 groups by lane&3)
            a += __shfl_xor_sync(0xffffffffu, a, 16);
            a += __shfl_xor_sync(0xffffffffu, a, 8);
            a += __shfl_xor_sync(0xffffffffu, a, 4);
            if (lane < 4) atomicAdd(&s_ps[c], a);
        }
    }
    __syncthreads();

    // ---- block -> global, release fence, completion ticket ----
    if (tid < CC) {
        atomicAdd(&g_ps[tid], s_ps[tid]);
        atomicAdd(&g_in[tid], s_in[tid]);
        atomicAdd(&g_ct[tid], s_ct[tid]);
        __threadfence();
    }
    __syncthreads();
    if (tid == 0)
        s_last = (atomicAdd(&g_tick, 1u) == NBLOCKS - 1);
    __syncthreads();

    // ---- last block finalizes, writes out, re-zeros for graph replay ----
    if (s_last && tid < 32) {
        __threadfence();   // acquire
        float l = 0.f, cnt = 0.f;
        if (tid < CC) {
            float ps = *(volatile float*)&g_ps[tid];
            float in = *(volatile float*)&g_in[tid];
            float ct = *(volatile float*)&g_ct[tid];
            float dice = (2.f * in + 1.f) / (ps + ct + 1.f);
            l   = 1.f - dice;
            cnt = ct;
            *(volatile float*)&g_ps[tid] = 0.f;
            *(volatile float*)&g_in[tid] = 0.f;
            *(volatile float*)&g_ct[tid] = 0.f;
        }
        #pragma unroll
        for (int o = 16; o > 0; o >>= 1) {
            l   += __shfl_xor_sync(0xffffffffu, l, o);
            cnt += __shfl_xor_sync(0xffffffffu, cnt, o);
        }
        if (tid == 0) {
            out[0] = (cnt > 0.f) ? l * (1.f / CC) : 0.f;
            *(volatile unsigned*)&g_tick = 0u;
        }
    }
}

extern "C" void kernel_launch(void* const* d_in, const int* in_sizes, int n_in,
                              void* d_out, int out_size) {
    const float* logits  = (const float*)d_in[0];
    const int*   targets = (const int*)d_in[1];
    float*       out     = (float*)d_out;
    dice_pipe<<<NBLOCKS, THREADS>>>(logits, targets, out);
}

// round 10
// speedup vs baseline: 2.0620x; 2.0620x over previous
#include <cuda_runtime.h>
#include <cuda_bf16.h>

// DiceLoss persistent kernel with cp.async double-buffered smem staging.
// logits [8,19,512,512] f32; targets [8,512,512] int32.
// 296 CTAs x 128 threads x 4 px/thread, 4096 tiles striped across CTAs.
// Each thread stages ITS OWN 19-class float4 slice via cp.async (no regs held,
// no scoreboard stalls, no __syncthreads in the loop) and accumulates
// probs_sum in registers; warp/shared/global reduction happens once at the end.

#define CC      19
#define LOG_HW  18
#define HW      (1 << LOG_HW)          // 262,144
#define NPIX    (8 * HW)               // 2,097,152
#define THREADS 128
#define PX      4
#define TILE_PX (THREADS * PX)         // 512
#define NTILES  (NPIX / TILE_PX)       // 4096
#define NBLOCKS 296                    // 2 CTAs/SM, single wave
#define IGN     255
#define SMEM_BYTES (2 * CC * THREADS * 16)   // 77,824 B (double buffer)

__device__ float    g_ps[CC];
__device__ float    g_in[CC];
__device__ float    g_ct[CC];
__device__ unsigned g_tick;

__device__ __forceinline__ void stage_tile(const float* __restrict__ logits,
                                           float4* __restrict__ dst, int tile, int tid)
{
    const int p  = tile * TILE_PX + tid * PX;
    const int b  = p >> LOG_HW;
    const int hw = p & (HW - 1);
    const float* gsrc = logits + (((size_t)b * CC) << LOG_HW) + hw;
    #pragma unroll
    for (int c = 0; c < CC; c++) {
        unsigned sa = (unsigned)__cvta_generic_to_shared(dst + c * THREADS);
        asm volatile("cp.async.cg.shared.global [%0], [%1], 16;"
                     :: "r"(sa), "l"(gsrc + ((size_t)c << LOG_HW)) : "memory");
    }
    asm volatile("cp.async.commit_group;" ::: "memory");
}

__global__ void __launch_bounds__(THREADS, 2) dice_async(
    const float* __restrict__ logits, const int* __restrict__ targets,
    float* __restrict__ out)
{
    extern __shared__ float4 sbuf[];           // [2][CC][THREADS]
    __shared__ float s_ps[CC], s_in[CC], s_ct[CC];
    __shared__ int   s_last;
    const int tid  = threadIdx.x;
    const int lane = tid & 31;
    if (tid < CC) { s_ps[tid] = 0.f; s_in[tid] = 0.f; s_ct[tid] = 0.f; }
    __syncthreads();

    float ps[CC];
    #pragma unroll
    for (int c = 0; c < CC; c++) ps[c] = 0.f;

    // ---- prologue: stage first tile, prefetch its targets ----
    int t = blockIdx.x;
    int4 tt;
    stage_tile(logits, sbuf + tid, t, tid);
    tt = *(const int4*)(targets + t * TILE_PX + tid * PX);

    int buf = 0;
    for (; t < NTILES; t += NBLOCKS) {
        const int tn = t + NBLOCKS;
        int4 tt_next;
        if (tn < NTILES) {
            stage_tile(logits, sbuf + (buf ^ 1) * CC * THREADS + tid, tn, tid);
            tt_next = *(const int4*)(targets + tn * TILE_PX + tid * PX);
            asm volatile("cp.async.wait_group 1;" ::: "memory");
        } else {
            asm volatile("cp.async.wait_group 0;" ::: "memory");
        }

        // ---- consume current tile (each thread reads only its own slots) ----
        const float4* src = sbuf + buf * CC * THREADS + tid;

        int t0 = tt.x, t1 = tt.y, t2 = tt.z, t3 = tt.w;
        float v0 = (t0 == IGN) ? 0.f : 1.f;
        float v1 = (t1 == IGN) ? 0.f : 1.f;
        float v2 = (t2 == IGN) ? 0.f : 1.f;
        float v3 = (t3 == IGN) ? 0.f : 1.f;
        t0 = (t0 == IGN || (unsigned)t0 >= CC) ? 0 : t0;
        t1 = (t1 == IGN || (unsigned)t1 >= CC) ? 0 : t1;
        t2 = (t2 == IGN || (unsigned)t2 >= CC) ? 0 : t2;
        t3 = (t3 == IGN || (unsigned)t3 >= CC) ? 0 : t3;

        __nv_bfloat162 e01[CC], e23[CC];
        float dx = 0.f, dy = 0.f, dz = 0.f, dw = 0.f;
        #pragma unroll
        for (int c = 0; c < CC; c++) {
            float4 xv = src[c * THREADS];
            float ex = __expf(xv.x), ey = __expf(xv.y);
            float ez = __expf(xv.z), ew = __expf(xv.w);
            dx += ex; dy += ey; dz += ez; dw += ew;
            e01[c] = __floats2bfloat162_rn(ex, ey);
            e23[c] = __floats2bfloat162_rn(ez, ew);
        }

        const float rx = v0 * __fdividef(1.f, dx);
        const float ry = v1 * __fdividef(1.f, dy);
        const float rz = v2 * __fdividef(1.f, dz);
        const float rw = v3 * __fdividef(1.f, dw);

        // gathered prob at true class: dynamic-index smem re-read (no SEL chains)
        const float ge0 = __expf(src[t0 * THREADS].x);
        const float ge1 = __expf(src[t1 * THREADS].y);
        const float ge2 = __expf(src[t2 * THREADS].z);
        const float ge3 = __expf(src[t3 * THREADS].w);

        atomicAdd(&s_in[t0], ge0 * rx);
        atomicAdd(&s_in[t1], ge1 * ry);
        atomicAdd(&s_in[t2], ge2 * rz);
        atomicAdd(&s_in[t3], ge3 * rw);
        atomicAdd(&s_ct[t0], v0);
        atomicAdd(&s_ct[t1], v1);
        atomicAdd(&s_ct[t2], v2);
        atomicAdd(&s_ct[t3], v3);

        // probs_sum: accumulate in registers (reduction deferred to the end)
        #pragma unroll
        for (int c = 0; c < CC; c++) {
            float2 p01 = __bfloat1622float2(e01[c]);
            float2 p23 = __bfloat1622float2(e23[c]);
            ps[c] += p01.x * rx + p01.y * ry + p23.x * rz + p23.y * rw;
        }

        if (tn < NTILES) tt = tt_next;
        buf ^= 1;
    }

    // ---- one-time reduction: warp shfl -> shared -> global ----
    #pragma unroll
    for (int c = 0; c < CC; c++) {
        float a = ps[c];
        #pragma unroll
        for (int o = 16; o > 0; o >>= 1)
            a += __shfl_xor_sync(0xffffffffu, a, o);
        if (lane == 0) atomicAdd(&s_ps[c], a);
    }
    __syncthreads();

    if (tid < CC) {
        atomicAdd(&g_ps[tid], s_ps[tid]);
        atomicAdd(&g_in[tid], s_in[tid]);
        atomicAdd(&g_ct[tid], s_ct[tid]);
        __threadfence();
    }
    __syncthreads();
    if (tid == 0)
        s_last = (atomicAdd(&g_tick, 1u) == NBLOCKS - 1);
    __syncthreads();

    if (s_last && tid < 32) {
        __threadfence();   // acquire
        float l = 0.f, cnt = 0.f;
        if (tid < CC) {
            float pssum = *(volatile float*)&g_ps[tid];
            float inter = *(volatile float*)&g_in[tid];
            float ct    = *(volatile float*)&g_ct[tid];
            float dice  = (2.f * inter + 1.f) / (pssum + ct + 1.f);
            l   = 1.f - dice;
            cnt = ct;
            *(volatile float*)&g_ps[tid] = 0.f;
            *(volatile float*)&g_in[tid] = 0.f;
            *(volatile float*)&g_ct[tid] = 0.f;
        }
        #pragma unroll
        for (int o = 16; o > 0; o >>= 1) {
            l   += __shfl_xor_sync(0xffffffffu, l, o);
            cnt += __shfl_xor_sync(0xffffffffu, cnt, o);
        }
        if (tid == 0) {
            out[0] = (cnt > 0.f) ? l * (1.f / CC) : 0.f;
            *(volatile unsigned*)&g_tick = 0u;
        }
    }
}

extern "C" void kernel_launch(void* const* d_in, const int* in_sizes, int n_in,
                              void* d_out, int out_size) {
    const float* logits  = (const float*)d_in[0];
    const int*   targets = (const int*)d_in[1];
    float*       out     = (float*)d_out;

    cudaFuncSetAttribute(dice_async, cudaFuncAttributeMaxDynamicSharedMemorySize,
                         SMEM_BYTES);
    dice_async<<<NBLOCKS, THREADS, SMEM_BYTES>>>(logits, targets, out);
}

// round 14
// speedup vs baseline: 2.4596x; 1.1929x over previous
#include <cuda_runtime.h>
#include <cuda_fp16.h>

// DiceLoss persistent kernel: cp.async double-buffered staging + fp16x2 exp.
// logits [8,19,512,512] f32; targets [8,512,512] int32.
// 296 CTAs x 256 threads x 2 px/thread; 4096 tiles striped across CTAs.
// 16 warps/SM (2 CTAs). ex2.approx.f16x2 does 2 pixels per MUFU op; probs_sum
// accumulates via one HFMA2/class; reduction deferred to kernel end.

#define CC      19
#define LOG_HW  18
#define HW      (1 << LOG_HW)          // 262,144
#define NPIX    (8 * HW)               // 2,097,152
#define THREADS 256
#define PX      2
#define TILE_PX (THREADS * PX)         // 512
#define NTILES  (NPIX / TILE_PX)       // 4096
#define NBLOCKS 296                    // 2 CTAs/SM, single wave
#define IGN     255
#define LOG2E   1.4426950408889634f
#define SMEM_BYTES (2 * CC * THREADS * 8)   // 77,824 B (double buffer, float2)

__device__ float    g_ps[CC];
__device__ float    g_in[CC];
__device__ float    g_ct[CC];
__device__ unsigned g_tick;

__device__ __forceinline__ void stage_tile(const float* __restrict__ logits,
                                           float2* __restrict__ dst, int tile, int tid)
{
    const int p  = tile * TILE_PX + tid * PX;
    const int b  = p >> LOG_HW;
    const int hw = p & (HW - 1);
    const float* gsrc = logits + (((size_t)b * CC) << LOG_HW) + hw;
    #pragma unroll
    for (int c = 0; c < CC; c++) {
        unsigned sa = (unsigned)__cvta_generic_to_shared(dst + c * THREADS);
        asm volatile("cp.async.ca.shared.global [%0], [%1], 8;"
                     :: "r"(sa), "l"(gsrc + ((size_t)c << LOG_HW)) : "memory");
    }
    asm volatile("cp.async.commit_group;" ::: "memory");
}

__device__ __forceinline__ __half2 h2_exp2(__half2 h) {
    unsigned hu = *reinterpret_cast<unsigned*>(&h), eu;
    asm("ex2.approx.f16x2 %0, %1;" : "=r"(eu) : "r"(hu));
    return *reinterpret_cast<__half2*>(&eu);
}

__global__ void __launch_bounds__(THREADS, 2) dice_h2(
    const float* __restrict__ logits, const int* __restrict__ targets,
    float* __restrict__ out)
{
    extern __shared__ float2 sbuf[];           // [2][CC][THREADS]
    __shared__ float s_ps[CC], s_in[CC], s_ct[CC];
    __shared__ int   s_last;
    const int tid  = threadIdx.x;
    const int lane = tid & 31;
    if (tid < CC) { s_ps[tid] = 0.f; s_in[tid] = 0.f; s_ct[tid] = 0.f; }
    __syncthreads();

    __half2 ps[CC];
    #pragma unroll
    for (int c = 0; c < CC; c++) ps[c] = __floats2half2_rn(0.f, 0.f);

    // ---- prologue ----
    int t = blockIdx.x;
    int2 tt;
    stage_tile(logits, sbuf + tid, t, tid);
    tt = *(const int2*)(targets + t * TILE_PX + tid * PX);

    int buf = 0;
    for (; t < NTILES; t += NBLOCKS) {
        const int tn = t + NBLOCKS;
        int2 tt_next;
        if (tn < NTILES) {
            stage_tile(logits, sbuf + (buf ^ 1) * CC * THREADS + tid, tn, tid);
            tt_next = *(const int2*)(targets + tn * TILE_PX + tid * PX);
            asm volatile("cp.async.wait_group 1;" ::: "memory");
        } else {
            asm volatile("cp.async.wait_group 0;" ::: "memory");
        }

        const float2* src = sbuf + buf * CC * THREADS + tid;

        int t0 = tt.x, t1 = tt.y;
        float v0 = (t0 == IGN) ? 0.f : 1.f;
        float v1 = (t1 == IGN) ? 0.f : 1.f;
        t0 = (t0 == IGN || (unsigned)t0 >= CC) ? 0 : t0;
        t1 = (t1 == IGN || (unsigned)t1 >= CC) ? 0 : t1;

        // ---- exp (fp16x2, 2 px per MUFU op) + 4-way packed denominators ----
        __half2 e[CC];
        __half2 acc[4];
        #pragma unroll
        for (int k = 0; k < 4; k++) acc[k] = __floats2half2_rn(0.f, 0.f);
        #pragma unroll
        for (int c = 0; c < CC; c++) {
            float2 xv = src[c * THREADS];
            __half2 h = __floats2half2_rn(xv.x * LOG2E, xv.y * LOG2E);
            __half2 ee = h2_exp2(h);
            e[c] = ee;
            acc[c & 3] = __hadd2(acc[c & 3], ee);
        }
        float2 a0 = __half22float2(acc[0]);
        float2 a1 = __half22float2(acc[1]);
        float2 a2 = __half22float2(acc[2]);
        float2 a3 = __half22float2(acc[3]);
        const float d0 = (a0.x + a1.x) + (a2.x + a3.x);
        const float d1 = (a0.y + a1.y) + (a2.y + a3.y);

        const float rx = v0 * __fdividef(1.f, d0);
        const float ry = v1 * __fdividef(1.f, d1);
        const __half2 rh = __floats2half2_rn(rx, ry);

        // ---- gather true-class prob (f32 path) + scatter atomics ----
        const float ge0 = __expf(src[t0 * THREADS].x);
        const float ge1 = __expf(src[t1 * THREADS].y);
        atomicAdd(&s_in[t0], ge0 * rx);
        atomicAdd(&s_in[t1], ge1 * ry);
        atomicAdd(&s_ct[t0], v0);
        atomicAdd(&s_ct[t1], v1);

        // ---- probs_sum: one HFMA2 per class ----
        #pragma unroll
        for (int c = 0; c < CC; c++)
            ps[c] = __hfma2(e[c], rh, ps[c]);

        if (tn < NTILES) tt = tt_next;
        buf ^= 1;
    }

    // ---- one-time reduction: warp shfl -> shared -> global ----
    #pragma unroll
    for (int c = 0; c < CC; c++) {
        float2 f = __half22float2(ps[c]);
        float a = f.x + f.y;
        #pragma unroll
        for (int o = 16; o > 0; o >>= 1)
            a += __shfl_xor_sync(0xffffffffu, a, o);
        if (lane == 0) atomicAdd(&s_ps[c], a);
    }
    __syncthreads();

    if (tid < CC) {
        atomicAdd(&g_ps[tid], s_ps[tid]);
        atomicAdd(&g_in[tid], s_in[tid]);
        atomicAdd(&g_ct[tid], s_ct[tid]);
        __threadfence();
    }
    __syncthreads();
    if (tid == 0)
        s_last = (atomicAdd(&g_tick, 1u) == NBLOCKS - 1);
    __syncthreads();

    if (s_last && tid < 32) {
        __threadfence();   // acquire
        float l = 0.f, cnt = 0.f;
        if (tid < CC) {
            float pssum = *(volatile float*)&g_ps[tid];
            float inter = *(volatile float*)&g_in[tid];
            float ct    = *(volatile float*)&g_ct[tid];
            float dice  = (2.f * inter + 1.f) / (pssum + ct + 1.f);
            l   = 1.f - dice;
            cnt = ct;
            *(volatile float*)&g_ps[tid] = 0.f;
            *(volatile float*)&g_in[tid] = 0.f;
            *(volatile float*)&g_ct[tid] = 0.f;
        }
        #pragma unroll
        for (int o = 16; o > 0; o >>= 1) {
            l   += __shfl_xor_sync(0xffffffffu, l, o);
            cnt += __shfl_xor_sync(0xffffffffu, cnt, o);
        }
        if (tid == 0) {
            out[0] = (cnt > 0.f) ? l * (1.f / CC) : 0.f;
            *(volatile unsigned*)&g_tick = 0u;
        }
    }
}

extern "C" void kernel_launch(void* const* d_in, const int* in_sizes, int n_in,
                              void* d_out, int out_size) {
    const float* logits  = (const float*)d_in[0];
    const int*   targets = (const int*)d_in[1];
    float*       out     = (float*)d_out;

    cudaFuncSetAttribute(dice_h2, cudaFuncAttributeMaxDynamicSharedMemorySize,
                         SMEM_BYTES);
    dice_h2<<<NBLOCKS, THREADS, SMEM_BYTES>>>(logits, targets, out);
}